// round 3
// baseline (speedup 1.0000x reference)
#include <cuda_runtime.h>
#include <stdint.h>

// MaxUnpooling2D, pool 2x2:
//   updates: [16,128,128,64] f32, mask: same shape int32 (flat idx into OH*OW*C)
//   out:     [16,256,256,64] f32, scatter-add (duplicates sum)
//
// dst = b*(OH*OW*C) + (mask & ~(C-1)) + c   with C=64, OH*OW*C = 1<<22
// src element index e: b = e>>20 (H*W*C = 1<<20), c = e & 63.

#define N_ELEMS   (16u * 128u * 128u * 64u)   // 16,777,216
#define OUT_ELEMS (16u * 256u * 256u * 64u)   // 67,108,864

__global__ void unpool_zero_kernel(float4* __restrict__ out) {
    unsigned i = blockIdx.x * blockDim.x + threadIdx.x;   // one float4 per thread
    out[i] = make_float4(0.f, 0.f, 0.f, 0.f);
}

__global__ void unpool_scatter_kernel(const float4* __restrict__ upd,
                                      const int4*   __restrict__ msk,
                                      float*        __restrict__ out) {
    unsigned i = blockIdx.x * blockDim.x + threadIdx.x;   // group of 4 elements
    float4 u = upd[i];
    int4   m = msk[i];

    unsigned e      = i << 2;                 // first element index of the group
    unsigned base_b = (e >> 20) << 22;        // batch offset in output
    unsigned c      = e & 63u;                // channel of first element (multiple of 4)

    atomicAdd(out + base_b + ((unsigned)m.x & ~63u) + c + 0u, u.x);
    atomicAdd(out + base_b + ((unsigned)m.y & ~63u) + c + 1u, u.y);
    atomicAdd(out + base_b + ((unsigned)m.z & ~63u) + c + 2u, u.z);
    atomicAdd(out + base_b + ((unsigned)m.w & ~63u) + c + 3u, u.w);
}

extern "C" void kernel_launch(void* const* d_in, const int* in_sizes, int n_in,
                              void* d_out, int out_size) {
    const float4* upd = (const float4*)d_in[0];
    const int4*   msk = (const int4*)d_in[1];
    float*        out = (float*)d_out;

    // Zero-fill: 67,108,864 floats = 16,777,216 float4s; 256 thr/blk -> 65536 blocks
    unsigned n4_out = OUT_ELEMS / 4u;
    unpool_zero_kernel<<<n4_out / 256u, 256u>>>((float4*)out);

    // Scatter: 16,777,216 elements / 4 per thread = 4,194,304 threads -> 16384 blocks
    unsigned n4_in = N_ELEMS / 4u;
    unpool_scatter_kernel<<<n4_in / 256u, 256u>>>(upd, msk, out);
}

// round 4
// speedup vs baseline: 1.4324x; 1.4324x over previous
#include <cuda_runtime.h>
#include <stdint.h>

// MaxUnpooling2D, pool 2x2, scatter-add:
//   updates: [16,128,128,64] f32, mask: same shape int32 (flat idx into OH*OW*C)
//   out:     [16,256,256,64] f32
//
// dst = (b << 22) + (mask & ~63) + c      (C=64, OH*OW*C = 1<<22, H*W*C = 1<<20)
//
// Phased execution: zero + scatter 2 batches at a time so the 33.5 MB output
// window stays resident in the 126 MB L2 — atomics RMW against L2-held zeroed
// lines instead of fetching from DRAM.

#define BATCHES         16u
#define IN_PER_BATCH    (1u << 20)          // 128*128*64
#define OUT_PER_BATCH   (1u << 22)          // 256*256*64
#define BATCH_PER_PHASE 2u
#define PHASES          (BATCHES / BATCH_PER_PHASE)   // 8

__global__ void unpool_zero_kernel(float4* __restrict__ out) {
    unsigned i = blockIdx.x * blockDim.x + threadIdx.x;
    out[i] = make_float4(0.f, 0.f, 0.f, 0.f);
}

__global__ void unpool_scatter_kernel(const float4* __restrict__ upd,
                                      const int4*   __restrict__ msk,
                                      float*        __restrict__ out,
                                      unsigned      group_base) {
    unsigned g = group_base + blockIdx.x * blockDim.x + threadIdx.x;  // group of 4 elems
    float4 u = upd[g];
    int4   m = msk[g];

    unsigned e      = g << 2;                 // first element index of the group
    unsigned base_b = (e >> 20) << 22;        // batch offset in output
    unsigned c      = e & 63u;                // channel (multiple of 4)

    float* ob = out + base_b + c;
    atomicAdd(ob + ((unsigned)m.x & ~63u) + 0u, u.x);
    atomicAdd(ob + ((unsigned)m.y & ~63u) + 1u, u.y);
    atomicAdd(ob + ((unsigned)m.z & ~63u) + 2u, u.z);
    atomicAdd(ob + ((unsigned)m.w & ~63u) + 3u, u.w);
}

extern "C" void kernel_launch(void* const* d_in, const int* in_sizes, int n_in,
                              void* d_out, int out_size) {
    const float4* upd = (const float4*)d_in[0];
    const int4*   msk = (const int4*)d_in[1];
    float*        out = (float*)d_out;

    const unsigned zero_f4_per_phase  = BATCH_PER_PHASE * OUT_PER_BATCH / 4u; // 2,097,152
    const unsigned groups_per_phase   = BATCH_PER_PHASE * IN_PER_BATCH  / 4u; //   524,288
    const unsigned zero_blocks        = zero_f4_per_phase / 256u;             //     8,192
    const unsigned scat_blocks        = groups_per_phase  / 256u;             //     2,048

    for (unsigned p = 0; p < PHASES; p++) {
        float4* ozone = (float4*)(out + (size_t)p * BATCH_PER_PHASE * OUT_PER_BATCH);
        unpool_zero_kernel<<<zero_blocks, 256u>>>(ozone);
        unpool_scatter_kernel<<<scat_blocks, 256u>>>(upd, msk, out,
                                                     p * groups_per_phase);
    }
}

// round 6
// speedup vs baseline: 1.6098x; 1.1239x over previous
#include <cuda_runtime.h>
#include <stdint.h>

// MaxUnpooling2D, pool 2x2, scatter-add:
//   updates: [16,128,128,64] f32, mask: same shape int32 (flat idx into OH*OW*C)
//   out:     [16,256,256,64] f32
//
// dst = (b << 22) + (mask & ~63) + c      (C=64, OH*OW*C = 1<<22, H*W*C = 1<<20)
//
// Phased execution (2 batches per phase) keeps the 33.5 MB output window L2-
// resident so atomics RMW in L2. Block-specialized fused kernel: first 2048
// blocks scatter phase p, next 2048 blocks zero phase p+1's window — the DRAM
// write stream (zero) overlaps the L2 atomic stream (scatter).

#define BATCHES         16u
#define IN_PER_BATCH    (1u << 20)          // 128*128*64
#define OUT_PER_BATCH   (1u << 22)          // 256*256*64
#define BATCH_PER_PHASE 2u
#define PHASES          (BATCHES / BATCH_PER_PHASE)   // 8

#define SCAT_BLOCKS     2048u               // 2048*256 threads * 4 elems = 2.1M
#define ZERO_BLOCKS     2048u               // 2048*256 threads * 4 float4 = 33.5MB
#define ZERO_T          (ZERO_BLOCKS * 256u)

__global__ void __launch_bounds__(256) unpool_zero_kernel(float4* __restrict__ out) {
    unsigned t = blockIdx.x * 256u + threadIdx.x;
    float4 z = make_float4(0.f, 0.f, 0.f, 0.f);
    out[t]              = z;
    out[t +     ZERO_T] = z;
    out[t + 2u * ZERO_T] = z;
    out[t + 3u * ZERO_T] = z;
}

__global__ void __launch_bounds__(256) unpool_fused_kernel(
        const float4* __restrict__ upd,
        const int4*   __restrict__ msk,
        float*        __restrict__ out,
        unsigned      group_base,      // first float4-group of this phase
        float4*       __restrict__ zwin,  // next phase's window (or null-op)
        int           do_zero) {
    if (blockIdx.x < SCAT_BLOCKS) {
        // ---- scatter phase p ----
        unsigned g = group_base + blockIdx.x * 256u + threadIdx.x;
        float4 u = upd[g];
        int4   m = msk[g];

        unsigned e      = g << 2;            // first element index of the group
        unsigned base_b = (e >> 20) << 22;   // batch offset in output
        unsigned c      = e & 63u;           // channel (multiple of 4)

        float* ob = out + base_b + c;
        atomicAdd(ob + ((unsigned)m.x & ~63u) + 0u, u.x);
        atomicAdd(ob + ((unsigned)m.y & ~63u) + 1u, u.y);
        atomicAdd(ob + ((unsigned)m.z & ~63u) + 2u, u.z);
        atomicAdd(ob + ((unsigned)m.w & ~63u) + 3u, u.w);
    } else if (do_zero) {
        // ---- zero window p+1 ----
        unsigned t = (blockIdx.x - SCAT_BLOCKS) * 256u + threadIdx.x;
        float4 z = make_float4(0.f, 0.f, 0.f, 0.f);
        zwin[t]               = z;
        zwin[t +      ZERO_T] = z;
        zwin[t + 2u * ZERO_T] = z;
        zwin[t + 3u * ZERO_T] = z;
    }
}

extern "C" void kernel_launch(void* const* d_in, const int* in_sizes, int n_in,
                              void* d_out, int out_size) {
    const float4* upd = (const float4*)d_in[0];
    const int4*   msk = (const int4*)d_in[1];
    float*        out = (float*)d_out;

    const unsigned groups_per_phase = BATCH_PER_PHASE * IN_PER_BATCH / 4u; // 524,288
    const size_t   win_elems        = (size_t)BATCH_PER_PHASE * OUT_PER_BATCH;

    // Prologue: zero window 0
    unpool_zero_kernel<<<ZERO_BLOCKS, 256u>>>((float4*)out);

    for (unsigned p = 0; p < PHASES; p++) {
        int do_zero = (p + 1u < PHASES);
        float4* zwin = (float4*)(out + (size_t)(p + 1u) * win_elems * (do_zero ? 1 : 0));
        unpool_fused_kernel<<<SCAT_BLOCKS + ZERO_BLOCKS, 256u>>>(
            upd, msk, out, p * groups_per_phase, zwin, do_zero);
    }
}